// round 13
// baseline (speedup 1.0000x reference)
#include <cuda_runtime.h>
#include <cuda_bf16.h>

// ---------------- problem constants ----------------
#define BB 16
#define LL 2048
#define TT (BB*LL)          // 32768 tokens
#define IND 57
#define DM 64
#define DI 128              // d_inner
#define HH 4                // heads
#define PP 32               // headdim
#define NN 32               // d_state
#define DXBC 192
#define DPROJ 324
#define QQ 32               // chunk length
#define NC (LL/QQ)          // 64 chunks per sequence
#define PT 32               // tokens per proj block
#define SEG 8               // chunks per scan segment
#define NSEG (NC/SEG)       // 8 segments

// ---------------- scratch (device globals; no runtime alloc) ----------------
__device__ float g_Wc[IND*DPROJ];     // fused W_lin@W_in
__device__ float g_bc[DPROJ];         // fused bias
__device__ float g_z[TT*DI];          // silu(z)
__device__ float g_xbc2[TT*DXBC];     // post conv+silu
__device__ float g_dt[TT*HH];         // softplus(dt + bias)
__device__ float g_alpha[BB*HH*LL];   // within-chunk inclusive cumsum of dt*A
__device__ float g_y[TT*DI];          // intra-chunk scan output
__device__ float g_S[BB*HH*NC*PP*NN]; // chunk-local states
__device__ float g_H0[BB*HH*NC*PP*NN];// segment-LOCAL state entering each chunk
__device__ float g_Sseg[BB*HH*NSEG*PP*NN]; // segment-end states
__device__ float g_carry[BB*HH*NSEG*PP*NN];// state entering each segment
__device__ float g_cdecay[BB*HH*NC];
__device__ float g_pool[BB*DI];

__device__ __forceinline__ float silu_f(float v) {
    return v / (1.f + __expf(-v));
}
__device__ __forceinline__ float softplus_f(float v) {
    return (v > 15.f) ? v : log1pf(__expf(v));
}

// ---------------- packed fp32x2 helpers (Blackwell FFMA2) ----------------
__device__ __forceinline__ float2 ffma2(float2 a, float2 b, float2 c) {
    unsigned long long ra = reinterpret_cast<unsigned long long&>(a);
    unsigned long long rb = reinterpret_cast<unsigned long long&>(b);
    unsigned long long rc = reinterpret_cast<unsigned long long&>(c);
    unsigned long long rd;
    asm("fma.rn.f32x2 %0, %1, %2, %3;" : "=l"(rd) : "l"(ra), "l"(rb), "l"(rc));
    return reinterpret_cast<float2&>(rd);
}
__device__ __forceinline__ float2 dup2(float v) {
    unsigned long long rd;
    asm("mov.b64 %0, {%1, %1};" : "=l"(rd) : "r"(__float_as_uint(v)));
    return reinterpret_cast<float2&>(rd);
}

// ---------------- K_pre: fused weight/bias + zero pool ----------------
__global__ void k_pre(const float* __restrict__ Wl,
                      const float* __restrict__ bl,
                      const float* __restrict__ Win) {
    if (blockIdx.x == 73) {
        for (int i = threadIdx.x; i < BB*DI; i += 256) g_pool[i] = 0.f;
        return;
    }
    int idx = blockIdx.x * 256 + threadIdx.x;
    if (idx < IND*DPROJ) {
        int k = idx / DPROJ, c = idx % DPROJ;
        float acc = 0.f;
        #pragma unroll 8
        for (int m = 0; m < DM; m++) acc += Wl[k*DM + m] * Win[m*DPROJ + c];
        g_Wc[idx] = acc;
    } else if (idx < IND*DPROJ + DPROJ) {
        int c = idx - IND*DPROJ;
        float acc = 0.f;
        #pragma unroll 8
        for (int m = 0; m < DM; m++) acc += bl[m] * Win[m*DPROJ + c];
        g_bc[c] = acc;
    }
}

// ---------------- K_proj: x -> (z, xBC[conv+silu], dt), FFMA2 tiles ----------------
__global__ void k_proj(const float* __restrict__ x,
                       const float* __restrict__ cw,
                       const float* __restrict__ cb,
                       const float* __restrict__ dt_bias) {
    __shared__ float sx[PT+3][IND];        // rows 0..2 halo, 3..34 main
    __shared__ float sxbc[PT+3][196];      // pre-conv xBC
    __shared__ float scw[DXBC*4];
    __shared__ float scb[DXBC];
    int tid = threadIdx.x;
    int t0  = blockIdx.x * PT;
    int l0  = t0 & (LL-1);

    for (int i = tid; i < PT*IND; i += 256) {
        int r = i / IND, k = i % IND;
        sx[r+3][k] = x[(size_t)(t0+r)*IND + k];
    }
    if (tid < 3*IND) {
        int r = tid / IND, k = tid % IND;
        sx[r][k] = (l0 - 3 + r >= 0) ? x[(size_t)(t0 - 3 + r)*IND + k] : 0.f;
    }
    for (int i = tid; i < DXBC*4; i += 256) scw[i] = cw[i];
    if (tid < DXBC) scb[tid] = cb[tid];
    __syncthreads();

    // halo pre-conv xBC (3 x 192)
    for (int e = tid; e < 3*DXBC; e += 256) {
        int r = e / DXBC, cc = e % DXBC;
        float acc = 0.f;
        if (l0 - 3 + r >= 0) {
            acc = g_bc[DI + cc];
            #pragma unroll 8
            for (int k = 0; k < IND; k++) acc += sx[r][k] * g_Wc[k*DPROJ + DI + cc];
        }
        sxbc[r][cc] = acc;
    }

    // main GEMM: 32 tokens x 324 cols, 4x4 tiles via packed FFMA2
    for (int tile = tid; tile < 8*81; tile += 256) {
        int tq = tile / 81, cq = tile % 81;
        int c0 = cq * 4;
        float2 a01[4] = {{0,0},{0,0},{0,0},{0,0}};
        float2 a23[4] = {{0,0},{0,0},{0,0},{0,0}};
        #pragma unroll 3
        for (int k = 0; k < IND; k++) {
            float4 w = *reinterpret_cast<const float4*>(g_Wc + k*DPROJ + c0);
            float2 w01 = {w.x, w.y}, w23 = {w.z, w.w};
            #pragma unroll
            for (int i = 0; i < 4; i++) {
                float2 hd = dup2(sx[3 + tq*4 + i][k]);
                a01[i] = ffma2(hd, w01, a01[i]);
                a23[i] = ffma2(hd, w23, a23[i]);
            }
        }
        float4 bcv = *reinterpret_cast<const float4*>(g_bc + c0);
        #pragma unroll
        for (int i = 0; i < 4; i++) {
            int tt = tq*4 + i;
            int tok = t0 + tt;
            float v4[4] = {a01[i].x + bcv.x, a01[i].y + bcv.y,
                           a23[i].x + bcv.z, a23[i].y + bcv.w};
            #pragma unroll
            for (int j = 0; j < 4; j++) {
                int cc = c0 + j;
                float v = v4[j];
                if (cc < DI) {
                    g_z[(size_t)tok*DI + cc] = silu_f(v);
                } else if (cc < DI + DXBC) {
                    sxbc[tt + 3][cc - DI] = v;
                } else {
                    int hd = cc - (DI + DXBC);
                    g_dt[(size_t)tok*HH + hd] = softplus_f(v + dt_bias[hd]);
                }
            }
        }
    }
    __syncthreads();

    // depthwise conv(4) + silu -> g_xbc2
    for (int e = tid; e < PT*DXBC; e += 256) {
        int t = e / DXBC, c = e % DXBC;
        float acc = scb[c];
        #pragma unroll
        for (int k = 0; k < 4; k++)
            acc += scw[c*4 + k] * sxbc[t + k][c];
        g_xbc2[(size_t)(t0+t)*DXBC + c] = silu_f(acc);
    }
}

// ---------------- K_phaseA: chunk-local scan, FFMA2 2x2 tiles ----------------
__global__ void k_phaseA(const float* __restrict__ A_log,
                         const float* __restrict__ Dp) {
    int bid = blockIdx.x;
    int c  = bid % NC;
    int bh = bid / NC;
    int hd = bh % HH;
    int b  = bh / HH;
    int tid = threadIdx.x;

    __shared__ __align__(16) float sx[QQ][34], sB[QQ][34], sC[QQ][34];
    __shared__ __align__(16) float sM[QQ][34], sxwT[QQ][34];
    __shared__ float sdt[QQ], salpha[QQ], sE[QQ], sF[QQ], sw_[QQ];

    size_t lbase = (size_t)b*LL + (size_t)c*QQ;

    {
        const float2* gsrc = reinterpret_cast<const float2*>(g_xbc2);
        for (int i = tid; i < 1536; i += 256) {
            int a = i >> 9, rem = i & 511;
            int r = rem >> 4, n2 = rem & 15;
            int offh = (a == 0) ? hd*16 : (a == 1 ? 64 : 80);
            float2 v = gsrc[(lbase + r)*96 + offh + n2];
            float* dst = (a == 0) ? &sx[0][0] : (a == 1 ? &sB[0][0] : &sC[0][0]);
            *reinterpret_cast<float2*>(dst + r*34 + 2*n2) = v;
        }
    }
    if (tid < QQ) {
        float A = -__expf(A_log[hd]);
        float v = g_dt[(lbase + tid)*HH + hd];
        sdt[tid] = v;
        float a = v * A;
        #pragma unroll
        for (int o = 1; o < 32; o <<= 1) {
            float n = __shfl_up_sync(0xffffffffu, a, o);
            if (tid >= o) a += n;
        }
        salpha[tid] = a;
        g_alpha[(size_t)bh*LL + c*QQ + tid] = a;
    }
    __syncthreads();
    if (tid < QQ) {
        float am = salpha[16];
        float al = salpha[tid];
        sE[tid]  = __expf(al - am);
        sF[tid]  = __expf(am - al) * sdt[tid];
        sw_[tid] = __expf(salpha[31] - al) * sdt[tid];
        if (tid == 0) g_cdecay[bid] = __expf(salpha[31]);
    }
    __syncthreads();

    int i = tid >> 4, j = tid & 15;

    // pass 1: packed dot products
    {
        float2 p00 = {0,0}, p10 = {0,0}, p11 = {0,0};
        #pragma unroll
        for (int n2 = 0; n2 < 16; n2++) {
            float2 c0 = *reinterpret_cast<float2*>(&sC[i][2*n2]);
            float2 c1 = *reinterpret_cast<float2*>(&sC[i+16][2*n2]);
            float2 b0 = *reinterpret_cast<float2*>(&sB[j][2*n2]);
            float2 b1 = *reinterpret_cast<float2*>(&sB[j+16][2*n2]);
            p00 = ffma2(c0, b0, p00);
            p10 = ffma2(c1, b0, p10);
            p11 = ffma2(c1, b1, p11);
        }
        float a00 = p00.x + p00.y, a10 = p10.x + p10.y, a11 = p11.x + p11.y;
        sM[i][j]       = (j <= i) ? a00 * sE[i]    * sF[j]    : 0.f;
        sM[i][j+16]    = 0.f;
        sM[i+16][j]    =            a10 * sE[i+16] * sF[j];
        sM[i+16][j+16] = (j <= i) ? a11 * sE[i+16] * sF[j+16] : 0.f;
    }
    for (int e = tid; e < QQ*32; e += 256) {
        int s = e >> 5, p = e & 31;
        sxwT[p][s] = sw_[s] * sx[s][p];
    }
    __syncthreads();

    // pass 2: Y[t][p]
    {
        float2 y0 = {0,0}, y1 = {0,0};
        int lim0 = (i >> 1) + 1;
        #pragma unroll 4
        for (int s2 = 0; s2 < lim0; s2++) {
            float2 m0 = *reinterpret_cast<float2*>(&sM[i][2*s2]);
            float2 m1 = *reinterpret_cast<float2*>(&sM[i+16][2*s2]);
            float2 x0 = *reinterpret_cast<float2*>(&sx[2*s2][2*j]);
            float2 x1 = *reinterpret_cast<float2*>(&sx[2*s2+1][2*j]);
            y0 = ffma2(dup2(m0.x), x0, y0);  y0 = ffma2(dup2(m0.y), x1, y0);
            y1 = ffma2(dup2(m1.x), x0, y1);  y1 = ffma2(dup2(m1.y), x1, y1);
        }
        #pragma unroll 4
        for (int s2 = lim0; s2 < lim0 + 8; s2++) {
            float2 m1 = *reinterpret_cast<float2*>(&sM[i+16][2*s2]);
            float2 x0 = *reinterpret_cast<float2*>(&sx[2*s2][2*j]);
            float2 x1 = *reinterpret_cast<float2*>(&sx[2*s2+1][2*j]);
            y1 = ffma2(dup2(m1.x), x0, y1);  y1 = ffma2(dup2(m1.y), x1, y1);
        }
        float2 Dh = dup2(Dp[hd]);
        float2 xt0 = *reinterpret_cast<float2*>(&sx[i][2*j]);
        float2 xt1 = *reinterpret_cast<float2*>(&sx[i+16][2*j]);
        y0 = ffma2(Dh, xt0, y0);
        y1 = ffma2(Dh, xt1, y1);
        *reinterpret_cast<float2*>(&g_y[(lbase + i   )*DI + hd*PP + 2*j]) = y0;
        *reinterpret_cast<float2*>(&g_y[(lbase + i+16)*DI + hd*PP + 2*j]) = y1;
    }
    // pass 3: S[p][n]
    {
        float2 s0 = {0,0}, s1 = {0,0};
        #pragma unroll
        for (int s2 = 0; s2 < 16; s2++) {
            float2 w0 = *reinterpret_cast<float2*>(&sxwT[i][2*s2]);
            float2 w1 = *reinterpret_cast<float2*>(&sxwT[i+16][2*s2]);
            float2 b0 = *reinterpret_cast<float2*>(&sB[2*s2][2*j]);
            float2 b1 = *reinterpret_cast<float2*>(&sB[2*s2+1][2*j]);
            s0 = ffma2(dup2(w0.x), b0, s0);  s0 = ffma2(dup2(w0.y), b1, s0);
            s1 = ffma2(dup2(w1.x), b0, s1);  s1 = ffma2(dup2(w1.y), b1, s1);
        }
        *reinterpret_cast<float2*>(&g_S[(size_t)bid*1024 + i*32      + 2*j]) = s0;
        *reinterpret_cast<float2*>(&g_S[(size_t)bid*1024 + (i+16)*32 + 2*j]) = s1;
    }
}

// ---------------- K_B1: segment-local scan, MLP=8 prefetch ----------------
__global__ void k_B1() {
    int bid = blockIdx.x;                 // ((bh*NSEG)+seg)*4 + pb
    int pb  = bid & 3;
    int sb  = bid >> 2;
    int seg = sb & (NSEG-1);
    int bh  = sb >> 3;
    int pn  = pb*256 + threadIdx.x;

    float s[SEG], d[SEG];
    #pragma unroll
    for (int c8 = 0; c8 < SEG; c8++)
        s[c8] = g_S[((size_t)bh*NC + seg*SEG + c8)*1024 + pn];
    #pragma unroll
    for (int c8 = 0; c8 < SEG; c8++)
        d[c8] = g_cdecay[bh*NC + seg*SEG + c8];

    float h = 0.f;
    #pragma unroll
    for (int c8 = 0; c8 < SEG; c8++) {
        g_H0[((size_t)bh*NC + seg*SEG + c8)*1024 + pn] = h;
        h = d[c8]*h + s[c8];
    }
    g_Sseg[((size_t)bh*NSEG + seg)*1024 + pn] = h;
}

// ---------------- K_B2: scan over segment aggregates, MLP=8 ----------------
__global__ void k_B2() {
    __shared__ float sdp[NSEG];
    int bid = blockIdx.x;                 // 0..255
    int bh  = bid >> 2;
    int pn  = (bid & 3)*256 + threadIdx.x;
    if (threadIdx.x < NSEG) {
        float p = 1.f;
        #pragma unroll
        for (int j = 0; j < SEG; j++)
            p *= g_cdecay[bh*NC + threadIdx.x*SEG + j];
        sdp[threadIdx.x] = p;
    }
    __syncthreads();
    float s[NSEG];
    #pragma unroll
    for (int seg = 0; seg < NSEG; seg++)
        s[seg] = g_Sseg[((size_t)bh*NSEG + seg)*1024 + pn];
    float h = 0.f;
    #pragma unroll
    for (int seg = 0; seg < NSEG; seg++) {
        g_carry[((size_t)bh*NSEG + seg)*1024 + pn] = h;
        h = sdp[seg]*h + s[seg];
    }
}

// ---------------- K_phaseCG: inter-chunk + gate + RMSNorm + pool (fused) ----------------
// block = (b, chunk c), all 4 heads; 256 threads
__global__ void k_phaseCG(const float* __restrict__ nw) {
    int bid = blockIdx.x;
    int c  = bid % NC;
    int b  = bid / NC;
    int tid = threadIdx.x;
    int seg = c >> 3;

    __shared__ __align__(16) float sHT[HH][NN][34]; // H transposed per head: [n][p]
    __shared__ __align__(16) float sC[QQ][34];
    __shared__ __align__(16) float sv[QQ][132];
    __shared__ float sea[HH][QQ];
    __shared__ float sdpre[HH];
    __shared__ float srms[QQ];

    size_t lbase = (size_t)b*LL + (size_t)c*QQ;

    if (c > 0) {
        if (tid < HH) {
            float dp = 1.f;
            for (int jj = seg*SEG; jj < c; jj++)
                dp *= g_cdecay[(b*HH + tid)*NC + jj];
            sdpre[tid] = dp;
        }
        if (tid < HH*QQ) {
            int hd = tid >> 5, t = tid & 31;
            sea[hd][t] = __expf(g_alpha[(size_t)(b*HH + hd)*LL + c*QQ + t]);
        }
        {
            const float2* gsrc = reinterpret_cast<const float2*>(g_xbc2);
            for (int i = tid; i < 512; i += 256) {
                int r = i >> 4, n2 = i & 15;
                float2 v = gsrc[(lbase + r)*96 + 80 + n2];
                *reinterpret_cast<float2*>(&sC[r][2*n2]) = v;
            }
        }
        __syncthreads();   // sdpre ready before H load uses it
        for (int e = tid; e < HH*PP*NN; e += 256) {
            int hd = e >> 10, r = e & 1023;
            int p = r >> 5, n = r & 31;
            size_t bhNC = (size_t)(b*HH + hd);
            float v = g_H0[(bhNC*NC + c)*1024 + r]
                    + sdpre[hd] * g_carry[(bhNC*NSEG + seg)*1024 + r];
            sHT[hd][n][p] = v;
        }
        __syncthreads();

        // inter-chunk contribution per head -> sv (raw, scaled later)
        int i = tid >> 4, j = tid & 15;
        #pragma unroll
        for (int hd = 0; hd < HH; hd++) {
            float2 a0 = {0,0}, a1 = {0,0};
            #pragma unroll
            for (int n2 = 0; n2 < 16; n2++) {
                float2 c0 = *reinterpret_cast<float2*>(&sC[i][2*n2]);
                float2 c1 = *reinterpret_cast<float2*>(&sC[i+16][2*n2]);
                float2 h0 = *reinterpret_cast<float2*>(&sHT[hd][2*n2][2*j]);
                float2 h1 = *reinterpret_cast<float2*>(&sHT[hd][2*n2+1][2*j]);
                a0 = ffma2(dup2(c0.x), h0, a0);  a0 = ffma2(dup2(c0.y), h1, a0);
                a1 = ffma2(dup2(c1.x), h0, a1);  a1 = ffma2(dup2(c1.y), h1, a1);
            }
            *reinterpret_cast<float2*>(&sv[i   ][hd*32 + 2*j]) = a0;
            *reinterpret_cast<float2*>(&sv[i+16][hd*32 + 2*j]) = a1;
        }
        __syncthreads();
    }

    // combine with intra y, gate with silu(z): sv = (y + sea*inter)*z
    for (int e = tid; e < QQ*32; e += 256) {
        int t = e >> 5, q = e & 31;
        size_t o = (lbase + t)*DI + q*4;
        float4 yv = *reinterpret_cast<const float4*>(&g_y[o]);
        float4 zv = *reinterpret_cast<const float4*>(&g_z[o]);
        float4 v;
        if (c > 0) {
            float se = sea[q >> 3][t];
            float4 it = *reinterpret_cast<float4*>(&sv[t][q*4]);
            v.x = (yv.x + se*it.x)*zv.x;  v.y = (yv.y + se*it.y)*zv.y;
            v.z = (yv.z + se*it.z)*zv.z;  v.w = (yv.w + se*it.w)*zv.w;
        } else {
            v.x = yv.x*zv.x;  v.y = yv.y*zv.y;
            v.z = yv.z*zv.z;  v.w = yv.w*zv.w;
        }
        *reinterpret_cast<float4*>(&sv[t][q*4]) = v;
    }
    __syncthreads();

    // RMS per token (8 warps x 4 tokens)
    {
        int w = tid >> 5, lane = tid & 31;
        #pragma unroll
        for (int tt = 0; tt < 4; tt++) {
            int t = w*4 + tt;
            float4 v = *reinterpret_cast<float4*>(&sv[t][lane*4]);
            float ss = v.x*v.x + v.y*v.y + v.z*v.z + v.w*v.w;
            #pragma unroll
            for (int o2 = 16; o2 > 0; o2 >>= 1)
                ss += __shfl_xor_sync(0xffffffffu, ss, o2);
            if (lane == 0) srms[t] = rsqrtf(ss*(1.f/DI) + 1e-5f);
        }
    }
    __syncthreads();

    // pool over the 32 tokens
    {
        int p  = tid & 127;
        int g2 = tid >> 7;
        float acc = 0.f;
        #pragma unroll 8
        for (int t = g2*16; t < g2*16 + 16; t++) acc += sv[t][p]*srms[t];
        atomicAdd(&g_pool[b*DI + p], acc*nw[p]);
    }
}

// ---------------- K_final: (pool/L) @ W_out @ W_cls + b_cls ----------------
__global__ void k_final(const float* __restrict__ Wout,
                        const float* __restrict__ Wcls,
                        const float* __restrict__ bcls,
                        float* __restrict__ out) {
    __shared__ float sp[BB][DI];
    __shared__ float st[BB][DM+1];
    int tid = threadIdx.x;
    for (int i = tid; i < BB*DI; i += 256)
        sp[i>>7][i&127] = g_pool[i] * (1.f/LL);
    __syncthreads();
    for (int i = tid; i < BB*DM; i += 256) {
        int bb = i >> 6, j = i & 63;
        float acc = 0.f;
        #pragma unroll 8
        for (int p = 0; p < DI; p++) acc += sp[bb][p]*Wout[p*DM + j];
        st[bb][j] = acc;
    }
    __syncthreads();
    if (tid < BB*6) {
        int bb = tid / 6, o = tid % 6;
        float acc = bcls[o];
        #pragma unroll 8
        for (int j = 0; j < DM; j++) acc += st[bb][j]*Wcls[j*6 + o];
        out[bb*6 + o] = acc;
    }
}

// ---------------- launcher ----------------
extern "C" void kernel_launch(void* const* d_in, const int* in_sizes, int n_in,
                              void* d_out, int out_size) {
    const float* x       = (const float*)d_in[0];
    const float* W_lin   = (const float*)d_in[1];
    const float* b_lin   = (const float*)d_in[2];
    const float* W_in    = (const float*)d_in[3];
    const float* conv_w  = (const float*)d_in[4];
    const float* conv_b  = (const float*)d_in[5];
    const float* dt_bias = (const float*)d_in[6];
    const float* A_log   = (const float*)d_in[7];
    const float* Dp      = (const float*)d_in[8];
    const float* norm_w  = (const float*)d_in[9];
    const float* W_out   = (const float*)d_in[10];
    const float* W_cls   = (const float*)d_in[11];
    const float* b_cls   = (const float*)d_in[12];
    float* out = (float*)d_out;

    k_pre<<<74, 256>>>(W_lin, b_lin, W_in);
    k_proj<<<TT/PT, 256>>>(x, conv_w, conv_b, dt_bias);
    k_phaseA<<<BB*HH*NC, 256>>>(A_log, Dp);
    k_B1<<<BB*HH*NSEG*4, 256>>>();
    k_B2<<<256, 256>>>();
    k_phaseCG<<<BB*NC, 256>>>(norm_w);
    k_final<<<1, 256>>>(W_out, W_cls, b_cls, out);
}

// round 14
// speedup vs baseline: 1.1120x; 1.1120x over previous
#include <cuda_runtime.h>
#include <cuda_bf16.h>

// ---------------- problem constants ----------------
#define BB 16
#define LL 2048
#define TT (BB*LL)          // 32768 tokens
#define IND 57
#define DM 64
#define DI 128              // d_inner
#define HH 4                // heads
#define PP 32               // headdim
#define NN 32               // d_state
#define DXBC 192
#define DPROJ 324
#define QQ 32               // chunk length
#define NC (LL/QQ)          // 64 chunks per sequence
#define PT 32               // tokens per proj block
#define SEG 8               // chunks per scan segment
#define NSEG (NC/SEG)       // 8 segments

// ---------------- scratch (device globals; no runtime alloc) ----------------
__device__ float g_Wc[IND*DPROJ];     // fused W_lin@W_in
__device__ float g_bc[DPROJ];         // fused bias
__device__ float g_z[TT*DI];          // silu(z)
__device__ float g_xbc2[TT*DXBC];     // post conv+silu
__device__ float g_dt[TT*HH];         // softplus(dt + bias)
__device__ float g_alpha[BB*HH*LL];   // within-chunk inclusive cumsum of dt*A
__device__ float g_y[TT*DI];          // intra-chunk scan output
__device__ float g_S[BB*HH*NC*PP*NN]; // chunk-local states
__device__ float g_H0[BB*HH*NC*PP*NN];// segment-LOCAL state entering each chunk
__device__ float g_Sseg[BB*HH*NSEG*PP*NN]; // segment-end states
__device__ float g_carry[BB*HH*NSEG*PP*NN];// state entering each segment
__device__ float g_cdecay[BB*HH*NC];
__device__ float g_pool[BB*DI];

__device__ __forceinline__ float silu_f(float v) {
    return v / (1.f + __expf(-v));
}
__device__ __forceinline__ float softplus_f(float v) {
    return (v > 15.f) ? v : log1pf(__expf(v));
}

// ---------------- packed fp32x2 helpers (Blackwell FFMA2) ----------------
__device__ __forceinline__ float2 ffma2(float2 a, float2 b, float2 c) {
    unsigned long long ra = reinterpret_cast<unsigned long long&>(a);
    unsigned long long rb = reinterpret_cast<unsigned long long&>(b);
    unsigned long long rc = reinterpret_cast<unsigned long long&>(c);
    unsigned long long rd;
    asm("fma.rn.f32x2 %0, %1, %2, %3;" : "=l"(rd) : "l"(ra), "l"(rb), "l"(rc));
    return reinterpret_cast<float2&>(rd);
}
__device__ __forceinline__ float2 dup2(float v) {
    unsigned long long rd;
    asm("mov.b64 %0, {%1, %1};" : "=l"(rd) : "r"(__float_as_uint(v)));
    return reinterpret_cast<float2&>(rd);
}

// ---------------- K_pre: fused weight/bias + zero pool ----------------
__global__ void k_pre(const float* __restrict__ Wl,
                      const float* __restrict__ bl,
                      const float* __restrict__ Win) {
    if (blockIdx.x == 73) {
        for (int i = threadIdx.x; i < BB*DI; i += 256) g_pool[i] = 0.f;
        return;
    }
    int idx = blockIdx.x * 256 + threadIdx.x;
    if (idx < IND*DPROJ) {
        int k = idx / DPROJ, c = idx % DPROJ;
        float acc = 0.f;
        #pragma unroll 8
        for (int m = 0; m < DM; m++) acc += Wl[k*DM + m] * Win[m*DPROJ + c];
        g_Wc[idx] = acc;
    } else if (idx < IND*DPROJ + DPROJ) {
        int c = idx - IND*DPROJ;
        float acc = 0.f;
        #pragma unroll 8
        for (int m = 0; m < DM; m++) acc += bl[m] * Win[m*DPROJ + c];
        g_bc[c] = acc;
    }
}

// ---------------- K_proj: x -> (z, xBC[conv+silu], dt), FFMA2 tiles ----------------
__global__ void k_proj(const float* __restrict__ x,
                       const float* __restrict__ cw,
                       const float* __restrict__ cb,
                       const float* __restrict__ dt_bias) {
    __shared__ float sx[PT+3][IND];        // rows 0..2 halo, 3..34 main
    __shared__ float sxbc[PT+3][196];      // pre-conv xBC
    __shared__ float scw[DXBC*4];
    __shared__ float scb[DXBC];
    int tid = threadIdx.x;
    int t0  = blockIdx.x * PT;
    int l0  = t0 & (LL-1);

    for (int i = tid; i < PT*IND; i += 256) {
        int r = i / IND, k = i % IND;
        sx[r+3][k] = x[(size_t)(t0+r)*IND + k];
    }
    if (tid < 3*IND) {
        int r = tid / IND, k = tid % IND;
        sx[r][k] = (l0 - 3 + r >= 0) ? x[(size_t)(t0 - 3 + r)*IND + k] : 0.f;
    }
    for (int i = tid; i < DXBC*4; i += 256) scw[i] = cw[i];
    if (tid < DXBC) scb[tid] = cb[tid];
    __syncthreads();

    // halo pre-conv xBC (3 x 192)
    for (int e = tid; e < 3*DXBC; e += 256) {
        int r = e / DXBC, cc = e % DXBC;
        float acc = 0.f;
        if (l0 - 3 + r >= 0) {
            acc = g_bc[DI + cc];
            #pragma unroll 8
            for (int k = 0; k < IND; k++) acc += sx[r][k] * g_Wc[k*DPROJ + DI + cc];
        }
        sxbc[r][cc] = acc;
    }

    // main GEMM: 32 tokens x 324 cols, 4x4 tiles via packed FFMA2
    for (int tile = tid; tile < 8*81; tile += 256) {
        int tq = tile / 81, cq = tile % 81;
        int c0 = cq * 4;
        float2 a01[4] = {{0,0},{0,0},{0,0},{0,0}};
        float2 a23[4] = {{0,0},{0,0},{0,0},{0,0}};
        #pragma unroll 3
        for (int k = 0; k < IND; k++) {
            float4 w = *reinterpret_cast<const float4*>(g_Wc + k*DPROJ + c0);
            float2 w01 = {w.x, w.y}, w23 = {w.z, w.w};
            #pragma unroll
            for (int i = 0; i < 4; i++) {
                float2 hd = dup2(sx[3 + tq*4 + i][k]);
                a01[i] = ffma2(hd, w01, a01[i]);
                a23[i] = ffma2(hd, w23, a23[i]);
            }
        }
        float4 bcv = *reinterpret_cast<const float4*>(g_bc + c0);
        #pragma unroll
        for (int i = 0; i < 4; i++) {
            int tt = tq*4 + i;
            int tok = t0 + tt;
            float v4[4] = {a01[i].x + bcv.x, a01[i].y + bcv.y,
                           a23[i].x + bcv.z, a23[i].y + bcv.w};
            #pragma unroll
            for (int j = 0; j < 4; j++) {
                int cc = c0 + j;
                float v = v4[j];
                if (cc < DI) {
                    g_z[(size_t)tok*DI + cc] = silu_f(v);
                } else if (cc < DI + DXBC) {
                    sxbc[tt + 3][cc - DI] = v;
                } else {
                    int hd = cc - (DI + DXBC);
                    g_dt[(size_t)tok*HH + hd] = softplus_f(v + dt_bias[hd]);
                }
            }
        }
    }
    __syncthreads();

    // depthwise conv(4) + silu -> g_xbc2
    for (int e = tid; e < PT*DXBC; e += 256) {
        int t = e / DXBC, c = e % DXBC;
        float acc = scb[c];
        #pragma unroll
        for (int k = 0; k < 4; k++)
            acc += scw[c*4 + k] * sxbc[t + k][c];
        g_xbc2[(size_t)(t0+t)*DXBC + c] = silu_f(acc);
    }
}

// ---------------- K_phaseA: chunk-local scan, 4x4 split passes ----------------
#define S36 36
__global__ void k_phaseA(const float* __restrict__ A_log,
                         const float* __restrict__ Dp) {
    int bid = blockIdx.x;
    int c  = bid % NC;
    int bh = bid / NC;
    int hd = bh % HH;
    int b  = bh / HH;
    int tid = threadIdx.x;

    __shared__ __align__(16) float sx[QQ][S36], sB[QQ][S36], sC[QQ][S36], sM[QQ][S36];
    __shared__ float sdt[QQ], salpha[QQ], sE[QQ], sF[QQ], sw_[QQ];

    size_t lbase = (size_t)b*LL + (size_t)c*QQ;

    // float4 global loads of x-slice, B, C (each 32x32)
    {
        const float4* gsrc = reinterpret_cast<const float4*>(g_xbc2); // 48 f4/token
        #pragma unroll
        for (int i = tid; i < 768; i += 256) {
            int a = i >> 8, rem = i & 255;
            int r = rem >> 3, q4 = rem & 7;
            int offq = (a == 0) ? hd*8 : (a == 1 ? 32 : 40);
            float4 v = gsrc[(lbase + r)*48 + offq + q4];
            float* dst = (a == 0) ? &sx[r][0] : (a == 1 ? &sB[r][0] : &sC[r][0]);
            *reinterpret_cast<float4*>(dst + 4*q4) = v;
        }
    }
    if (tid < QQ) {
        float A = -__expf(A_log[hd]);
        float v = g_dt[(lbase + tid)*HH + hd];
        sdt[tid] = v;
        float a = v * A;
        #pragma unroll
        for (int o = 1; o < 32; o <<= 1) {
            float n = __shfl_up_sync(0xffffffffu, a, o);
            if (tid >= o) a += n;
        }
        salpha[tid] = a;
        g_alpha[(size_t)bh*LL + c*QQ + tid] = a;
    }
    __syncthreads();
    if (tid < QQ) {
        float am = salpha[16];
        float al = salpha[tid];
        sE[tid]  = __expf(al - am);
        sF[tid]  = __expf(am - al) * sdt[tid];
        sw_[tid] = __expf(salpha[31] - al) * sdt[tid];
        if (tid == 0) g_cdecay[bid] = __expf(salpha[31]);
    }
    __syncthreads();

    // ---- Phase I: pass1 (warps 0-1) and pass3 (warps 2-3) concurrently ----
    if (tid < 64) {
        // pass1: M[t][s] = (C_t.B_s)*E[t]*F[s], lower tri; 4x4 tile
        int i4 = tid >> 3, j4 = tid & 7;   // rows {i4+8k}, cols {j4+8m}
        float2 acc[4][4];
        #pragma unroll
        for (int a = 0; a < 4; a++)
            #pragma unroll
            for (int bq = 0; bq < 4; bq++) acc[a][bq] = make_float2(0.f, 0.f);
        #pragma unroll
        for (int n4 = 0; n4 < 8; n4++) {
            float4 cr[4], br[4];
            #pragma unroll
            for (int k = 0; k < 4; k++) {
                cr[k] = *reinterpret_cast<float4*>(&sC[i4 + 8*k][4*n4]);
                br[k] = *reinterpret_cast<float4*>(&sB[j4 + 8*k][4*n4]);
            }
            #pragma unroll
            for (int a = 0; a < 4; a++) {
                float2 clo = {cr[a].x, cr[a].y}, chi = {cr[a].z, cr[a].w};
                #pragma unroll
                for (int bq = 0; bq < 4; bq++) {
                    float2 blo = {br[bq].x, br[bq].y}, bhi = {br[bq].z, br[bq].w};
                    acc[a][bq] = ffma2(clo, blo, acc[a][bq]);
                    acc[a][bq] = ffma2(chi, bhi, acc[a][bq]);
                }
            }
        }
        #pragma unroll
        for (int a = 0; a < 4; a++) {
            int t = i4 + 8*a;
            float Et = sE[t];
            #pragma unroll
            for (int bq = 0; bq < 4; bq++) {
                int s = j4 + 8*bq;
                float m = (s <= t) ? (acc[a][bq].x + acc[a][bq].y) * Et * sF[s] : 0.f;
                sM[t][s] = m;
            }
        }
    } else if (tid < 128) {
        // pass3: S[p][n] = sum_s x[s][p] * (w_s * B[s][n]); 4x4 tile
        int t2 = tid - 64;
        int pa = t2 >> 3, na = t2 & 7;     // p base 4*pa, n base 4*na
        float2 a0[4], a1[4];
        #pragma unroll
        for (int k = 0; k < 4; k++) { a0[k] = make_float2(0.f,0.f); a1[k] = make_float2(0.f,0.f); }
        #pragma unroll 8
        for (int s = 0; s < QQ; s++) {
            float ws = sw_[s];
            float4 xv = *reinterpret_cast<float4*>(&sx[s][4*pa]);
            float4 bv = *reinterpret_cast<float4*>(&sB[s][4*na]);
            float2 wlo = {bv.x*ws, bv.y*ws};
            float2 whi = {bv.z*ws, bv.w*ws};
            float xd[4] = {xv.x, xv.y, xv.z, xv.w};
            #pragma unroll
            for (int k = 0; k < 4; k++) {
                float2 xdd = dup2(xd[k]);
                a0[k] = ffma2(xdd, wlo, a0[k]);
                a1[k] = ffma2(xdd, whi, a1[k]);
            }
        }
        #pragma unroll
        for (int k = 0; k < 4; k++) {
            float4 o = {a0[k].x, a0[k].y, a1[k].x, a1[k].y};
            *reinterpret_cast<float4*>(&g_S[(size_t)bid*1024 + (4*pa+k)*32 + 4*na]) = o;
        }
    }
    __syncthreads();

    // ---- pass2: Y[t][p] = D*x + sum_s M[t][s] x[s][p]; t {i,i+16}, p {2j,2j+1} ----
    {
        int i = tid >> 4, j = tid & 15;
        float2 y0 = {0,0}, y1 = {0,0};
        int lim = i >> 2;
        for (int s4 = 0; s4 <= lim; s4++) {
            float4 m0 = *reinterpret_cast<float4*>(&sM[i][4*s4]);
            float4 m1 = *reinterpret_cast<float4*>(&sM[i+16][4*s4]);
            float2 x0 = *reinterpret_cast<float2*>(&sx[4*s4+0][2*j]);
            float2 x1 = *reinterpret_cast<float2*>(&sx[4*s4+1][2*j]);
            float2 x2 = *reinterpret_cast<float2*>(&sx[4*s4+2][2*j]);
            float2 x3 = *reinterpret_cast<float2*>(&sx[4*s4+3][2*j]);
            y0 = ffma2(dup2(m0.x), x0, y0); y0 = ffma2(dup2(m0.y), x1, y0);
            y0 = ffma2(dup2(m0.z), x2, y0); y0 = ffma2(dup2(m0.w), x3, y0);
            y1 = ffma2(dup2(m1.x), x0, y1); y1 = ffma2(dup2(m1.y), x1, y1);
            y1 = ffma2(dup2(m1.z), x2, y1); y1 = ffma2(dup2(m1.w), x3, y1);
        }
        #pragma unroll
        for (int s4 = lim+1; s4 <= lim+4; s4++) {
            float4 m1 = *reinterpret_cast<float4*>(&sM[i+16][4*s4]);
            float2 x0 = *reinterpret_cast<float2*>(&sx[4*s4+0][2*j]);
            float2 x1 = *reinterpret_cast<float2*>(&sx[4*s4+1][2*j]);
            float2 x2 = *reinterpret_cast<float2*>(&sx[4*s4+2][2*j]);
            float2 x3 = *reinterpret_cast<float2*>(&sx[4*s4+3][2*j]);
            y1 = ffma2(dup2(m1.x), x0, y1); y1 = ffma2(dup2(m1.y), x1, y1);
            y1 = ffma2(dup2(m1.z), x2, y1); y1 = ffma2(dup2(m1.w), x3, y1);
        }
        float2 Dh = dup2(Dp[hd]);
        float2 xt0 = *reinterpret_cast<float2*>(&sx[i][2*j]);
        float2 xt1 = *reinterpret_cast<float2*>(&sx[i+16][2*j]);
        y0 = ffma2(Dh, xt0, y0);
        y1 = ffma2(Dh, xt1, y1);
        *reinterpret_cast<float2*>(&g_y[(lbase + i   )*DI + hd*PP + 2*j]) = y0;
        *reinterpret_cast<float2*>(&g_y[(lbase + i+16)*DI + hd*PP + 2*j]) = y1;
    }
}

// ---------------- K_B1: segment-local scan, MLP=8 prefetch ----------------
__global__ void k_B1() {
    int bid = blockIdx.x;                 // ((bh*NSEG)+seg)*4 + pb
    int pb  = bid & 3;
    int sb  = bid >> 2;
    int seg = sb & (NSEG-1);
    int bh  = sb >> 3;
    int pn  = pb*256 + threadIdx.x;

    float s[SEG], d[SEG];
    #pragma unroll
    for (int c8 = 0; c8 < SEG; c8++)
        s[c8] = g_S[((size_t)bh*NC + seg*SEG + c8)*1024 + pn];
    #pragma unroll
    for (int c8 = 0; c8 < SEG; c8++)
        d[c8] = g_cdecay[bh*NC + seg*SEG + c8];

    float h = 0.f;
    #pragma unroll
    for (int c8 = 0; c8 < SEG; c8++) {
        g_H0[((size_t)bh*NC + seg*SEG + c8)*1024 + pn] = h;
        h = d[c8]*h + s[c8];
    }
    g_Sseg[((size_t)bh*NSEG + seg)*1024 + pn] = h;
}

// ---------------- K_B2: scan over segment aggregates, MLP=8 ----------------
__global__ void k_B2() {
    __shared__ float sdp[NSEG];
    int bid = blockIdx.x;                 // 0..255
    int bh  = bid >> 2;
    int pn  = (bid & 3)*256 + threadIdx.x;
    if (threadIdx.x < NSEG) {
        float p = 1.f;
        #pragma unroll
        for (int j = 0; j < SEG; j++)
            p *= g_cdecay[bh*NC + threadIdx.x*SEG + j];
        sdp[threadIdx.x] = p;
    }
    __syncthreads();
    float s[NSEG];
    #pragma unroll
    for (int seg = 0; seg < NSEG; seg++)
        s[seg] = g_Sseg[((size_t)bh*NSEG + seg)*1024 + pn];
    float h = 0.f;
    #pragma unroll
    for (int seg = 0; seg < NSEG; seg++) {
        g_carry[((size_t)bh*NSEG + seg)*1024 + pn] = h;
        h = sdp[seg]*h + s[seg];
    }
}

// ---------------- K_phaseC: inter-chunk contribution (combines carry) ----------------
__global__ void k_phaseC() {
    int bid = blockIdx.x;
    int c  = bid % NC;
    if (c == 0) return;                   // incoming state is zero
    int bh = bid / NC;
    int hd = bh % HH;
    int b  = bh / HH;
    int tid = threadIdx.x;
    int seg = c >> 3;

    __shared__ __align__(16) float sHT[NN][34];  // H transposed: [n][p]
    __shared__ __align__(16) float sC[QQ][34];
    __shared__ float sea[QQ];

    size_t lbase = (size_t)b*LL + (size_t)c*QQ;

    // within-segment prefix decay product (<=7 warp-uniform L1 loads)
    float dpre = 1.f;
    for (int jj = seg*SEG; jj < c; jj++) dpre *= g_cdecay[bh*NC + jj];

    for (int e = tid; e < PP*NN; e += 256) {
        float v = g_H0[(size_t)bid*1024 + e]
                + dpre * g_carry[((size_t)bh*NSEG + seg)*1024 + e];
        sHT[e & 31][e >> 5] = v;
    }
    {
        const float2* gsrc = reinterpret_cast<const float2*>(g_xbc2);
        for (int i = tid; i < 512; i += 256) {
            int r = i >> 4, n2 = i & 15;
            float2 v = gsrc[(lbase + r)*96 + 80 + n2];
            *reinterpret_cast<float2*>(&sC[r][2*n2]) = v;
        }
    }
    if (tid < QQ) sea[tid] = __expf(g_alpha[(size_t)bh*LL + c*QQ + tid]);
    __syncthreads();

    int i = tid >> 4, j = tid & 15;
    float2 a0 = {0,0}, a1 = {0,0};
    #pragma unroll
    for (int n2 = 0; n2 < 16; n2++) {
        float2 c0 = *reinterpret_cast<float2*>(&sC[i][2*n2]);
        float2 c1 = *reinterpret_cast<float2*>(&sC[i+16][2*n2]);
        float2 h0 = *reinterpret_cast<float2*>(&sHT[2*n2][2*j]);
        float2 h1 = *reinterpret_cast<float2*>(&sHT[2*n2+1][2*j]);
        a0 = ffma2(dup2(c0.x), h0, a0);  a0 = ffma2(dup2(c0.y), h1, a0);
        a1 = ffma2(dup2(c1.x), h0, a1);  a1 = ffma2(dup2(c1.y), h1, a1);
    }
    {
        float2* yp = reinterpret_cast<float2*>(&g_y[(lbase + i)*DI + hd*PP + 2*j]);
        *yp = ffma2(dup2(sea[i]), a0, *yp);
    }
    {
        float2* yp = reinterpret_cast<float2*>(&g_y[(lbase + i+16)*DI + hd*PP + 2*j]);
        *yp = ffma2(dup2(sea[i+16]), a1, *yp);
    }
}

// ---------------- K_gate_pool: y*silu(z), RMSNorm, pool over L ----------------
__global__ void k_gate_pool(const float* __restrict__ nw) {
    __shared__ float sv[64][132];
    __shared__ float srms[64];
    int b   = blockIdx.x >> 5;
    int lt0 = (blockIdx.x & 31) << 6;
    int tid  = threadIdx.x;
    int w    = tid >> 5;
    int lane = tid & 31;

    #pragma unroll
    for (int tt = 0; tt < 8; tt++) {
        int t = w*8 + tt;
        size_t o = ((size_t)b*LL + lt0 + t)*DI + lane*4;
        float4 yv = *reinterpret_cast<const float4*>(&g_y[o]);
        float4 zv = *reinterpret_cast<const float4*>(&g_z[o]);
        float4 v = {yv.x*zv.x, yv.y*zv.y, yv.z*zv.z, yv.w*zv.w};
        *reinterpret_cast<float4*>(&sv[t][lane*4]) = v;
        float ss = v.x*v.x + v.y*v.y + v.z*v.z + v.w*v.w;
        #pragma unroll
        for (int o2 = 16; o2 > 0; o2 >>= 1)
            ss += __shfl_xor_sync(0xffffffffu, ss, o2);
        if (lane == 0) srms[t] = rsqrtf(ss*(1.f/DI) + 1e-5f);
    }
    __syncthreads();

    int p  = tid & 127;
    int g2 = tid >> 7;
    float acc = 0.f;
    #pragma unroll 8
    for (int t = g2*32; t < g2*32 + 32; t++) acc += sv[t][p]*srms[t];
    atomicAdd(&g_pool[b*DI + p], acc*nw[p]);
}

// ---------------- K_final: (pool/L) @ W_out @ W_cls + b_cls ----------------
__global__ void k_final(const float* __restrict__ Wout,
                        const float* __restrict__ Wcls,
                        const float* __restrict__ bcls,
                        float* __restrict__ out) {
    __shared__ float sp[BB][DI];
    __shared__ float st[BB][DM+1];
    int tid = threadIdx.x;
    for (int i = tid; i < BB*DI; i += 256)
        sp[i>>7][i&127] = g_pool[i] * (1.f/LL);
    __syncthreads();
    for (int i = tid; i < BB*DM; i += 256) {
        int bb = i >> 6, j = i & 63;
        float acc = 0.f;
        #pragma unroll 8
        for (int p = 0; p < DI; p++) acc += sp[bb][p]*Wout[p*DM + j];
        st[bb][j] = acc;
    }
    __syncthreads();
    if (tid < BB*6) {
        int bb = tid / 6, o = tid % 6;
        float acc = bcls[o];
        #pragma unroll 8
        for (int j = 0; j < DM; j++) acc += st[bb][j]*Wcls[j*6 + o];
        out[bb*6 + o] = acc;
    }
}

// ---------------- launcher ----------------
extern "C" void kernel_launch(void* const* d_in, const int* in_sizes, int n_in,
                              void* d_out, int out_size) {
    const float* x       = (const float*)d_in[0];
    const float* W_lin   = (const float*)d_in[1];
    const float* b_lin   = (const float*)d_in[2];
    const float* W_in    = (const float*)d_in[3];
    const float* conv_w  = (const float*)d_in[4];
    const float* conv_b  = (const float*)d_in[5];
    const float* dt_bias = (const float*)d_in[6];
    const float* A_log   = (const float*)d_in[7];
    const float* Dp      = (const float*)d_in[8];
    const float* norm_w  = (const float*)d_in[9];
    const float* W_out   = (const float*)d_in[10];
    const float* W_cls   = (const float*)d_in[11];
    const float* b_cls   = (const float*)d_in[12];
    float* out = (float*)d_out;

    k_pre<<<74, 256>>>(W_lin, b_lin, W_in);
    k_proj<<<TT/PT, 256>>>(x, conv_w, conv_b, dt_bias);
    k_phaseA<<<BB*HH*NC, 256>>>(A_log, Dp);
    k_B1<<<BB*HH*NSEG*4, 256>>>();
    k_B2<<<256, 256>>>();
    k_phaseC<<<BB*HH*NC, 256>>>();
    k_gate_pool<<<BB*(LL/64), 256>>>(norm_w);
    k_final<<<1, 256>>>(W_out, W_cls, b_cls, out);
}